// round 16
// baseline (speedup 1.0000x reference)
#include <cuda_runtime.h>
#include <cuda_bf16.h>
#include <cstdint>

#define SEQ   65536
#define HID   1024
#define EMB   512
#define NCH   512
#define SCTA  128        // scan CTAs
#define SROW  8          // rows per scan CTA

// ---------------- device scratch (static allocation only) ----------------
__device__ __align__(16) float    g_hv[2][HID];    // ping-pong h values (no tags)
__device__ __align__(128) unsigned g_flag[SCTA][32]; // 1 flag per publisher CTA, own 128B line
__device__ float g_xp[(size_t)SEQ * HID];          // x projections  (256 MB)
__device__ float g_hs[(size_t)SEQ * HID];          // hidden states  (256 MB)

// ---------------- helpers (b32 twins of the proven b64 relaxed ops) -------
__device__ __forceinline__ void st_f32_rlx(float* p, float v) {
    asm volatile("st.global.relaxed.gpu.b32 [%0], %1;"
                 :: "l"(p), "r"(__float_as_uint(v)) : "memory");
}
__device__ __forceinline__ void st_u32_rlx(unsigned* p, unsigned v) {
    asm volatile("st.global.relaxed.gpu.b32 [%0], %1;" :: "l"(p), "r"(v) : "memory");
}
__device__ __forceinline__ unsigned ld_u32_rlx(const unsigned* p) {
    unsigned u;
    asm volatile("ld.global.relaxed.gpu.b32 %0, [%1];" : "=r"(u) : "l"(p) : "memory");
    return u;
}
__device__ __forceinline__ float ld_f32_rlx(const float* p) {
    unsigned u;
    asm volatile("ld.global.relaxed.gpu.b32 %0, [%1];" : "=r"(u) : "l"(p) : "memory");
    return __uint_as_float(u);
}

// ---------------- init: clear flags each launch (graph replays!) ----------
__global__ void init_tags_kernel() {
    unsigned* p = &g_flag[0][0];
    for (int i = threadIdx.x; i < SCTA * 32; i += blockDim.x) p[i] = 0u;
}

// ---------------- fp32 SGEMM:  C[M,N] = A[M,K] * B[N,K]^T (+bias) ---------
template<bool GATHER, bool BIAS>
__global__ void __launch_bounds__(256) sgemm_tn(
    const float* __restrict__ A, const float* __restrict__ B,
    float* __restrict__ C, const int* __restrict__ idx,
    const float* __restrict__ bias, int M, int N, int K)
{
    __shared__ __align__(16) float As[8][132];
    __shared__ __align__(16) float Bs[8][132];
    __shared__ int sidx[128];

    const int tid = threadIdx.x;
    const int bm  = blockIdx.y * 128;
    const int bn  = blockIdx.x * 128;

    if (GATHER && tid < 128) sidx[tid] = idx[bm + tid];
    __syncthreads();

    const int tx = tid & 15;
    const int ty = tid >> 4;
    const int arow = tid >> 1;
    const int akq  = (tid & 1) * 4;

    const float* Arow = GATHER ? (A + (size_t)sidx[arow] * K)
                               : (A + (size_t)(bm + arow) * K);
    const float* Brow = B + (size_t)(bn + arow) * K;

    float acc[8][8];
    #pragma unroll
    for (int i = 0; i < 8; i++)
        #pragma unroll
        for (int j = 0; j < 8; j++) acc[i][j] = 0.f;

    for (int kt = 0; kt < K; kt += 8) {
        float4 av = *(const float4*)(Arow + kt + akq);
        float4 bv = *(const float4*)(Brow + kt + akq);
        __syncthreads();
        As[akq+0][arow] = av.x; As[akq+1][arow] = av.y;
        As[akq+2][arow] = av.z; As[akq+3][arow] = av.w;
        Bs[akq+0][arow] = bv.x; Bs[akq+1][arow] = bv.y;
        Bs[akq+2][arow] = bv.z; Bs[akq+3][arow] = bv.w;
        __syncthreads();
        #pragma unroll
        for (int k = 0; k < 8; k++) {
            float ra[8], rb[8];
            #pragma unroll
            for (int i = 0; i < 8; i++) ra[i] = As[k][ty * 8 + i];
            #pragma unroll
            for (int j = 0; j < 8; j++) rb[j] = Bs[k][tx * 8 + j];
            #pragma unroll
            for (int i = 0; i < 8; i++)
                #pragma unroll
                for (int j = 0; j < 8; j++) acc[i][j] += ra[i] * rb[j];
        }
    }

    float bload[8];
    #pragma unroll
    for (int j = 0; j < 8; j++) bload[j] = BIAS ? bias[bn + tx * 8 + j] : 0.f;

    #pragma unroll
    for (int i = 0; i < 8; i++) {
        size_t row = (size_t)(bm + ty * 8 + i);
        float* cp = C + row * N + bn + tx * 8;
        float4 v0, v1;
        v0.x = acc[i][0] + bload[0]; v0.y = acc[i][1] + bload[1];
        v0.z = acc[i][2] + bload[2]; v0.w = acc[i][3] + bload[3];
        v1.x = acc[i][4] + bload[4]; v1.y = acc[i][5] + bload[5];
        v1.z = acc[i][6] + bload[6]; v1.w = acc[i][7] + bload[7];
        *(float4*)(cp)     = v0;
        *(float4*)(cp + 4) = v1;
    }
}

// ---------------- the scan ----------------
// 128 CTAs x 1024 threads, 8 rows per CTA. EXACT R2 compute/barrier
// skeleton (measured best: 74.3 ms); only the publish/detect protocol is
// changed to unload the L2 (old: 131072 threads re-polling 8B pairs every
// RTT ~= 524 sector-req/cyc >> ~200/cyc LTS capacity -> queue-inflated
// detect. New: 16384 pollers on 128 dedicated lines ~= 65 req/cyc).
//   Publish (end of step s): threads tid<8 store h_{s+1} values (relaxed),
//   __syncwarp, tid0: __threadfence + flag[cta] = s+1 (monotone).
//   Detect (start of step s): threads tid<128: poll flag[tid] >= s, then
//   __threadfence, then single-shot load that CTA's 8 values -> sh.
//   bar0, R2 compute (warps 0..15, 2rowx8col, LDS.128, butterfly, sred),
//   bar1, finalize tid<8 (combine, tanh, publish).
// Ordering: data st.relaxed -> syncwarp -> fence -> flag st.relaxed ->
// (consumer) flag ld.relaxed -> fence -> data ld.relaxed: fence-fence sync.
// Slot WAR: publisher of h_{s+2} needs all flags >= s+1 => every CTA
// finished step s (data reads included) before slot s&1 is overwritten.
__global__ void __launch_bounds__(1024, 1) scan_kernel(const float* __restrict__ Waa)
{
    __shared__ __align__(16) float sh[HID];          // staged h_t
    __shared__ float sred[SROW][4];                  // [row][quarter]

    const int tid = threadIdx.x;
    const int w = tid >> 5, l = tid & 31;
    const int row0 = blockIdx.x * SROW;
    const bool is_compute = (w < 16);
    const int p = (w >> 2) & 3;          // row-pair 0..3
    const int q = w & 3;                 // column quarter
    const int c0 = q * 256 + l * 8;      // this lane's column base

    // weights: 2 rows x 8 cols per compute thread (coalesced one-time load)
    float4 w0a, w0b, w1a, w1b;
    if (is_compute) {
        const float* base = Waa + (size_t)(row0 + 2 * p) * HID + c0;
        w0a = *(const float4*)(base);
        w0b = *(const float4*)(base + 4);
        w1a = *(const float4*)(base + HID);
        w1b = *(const float4*)(base + HID + 4);
    }

    // step 0: h_1 = tanh(xp[0]) (h_0 == 0 -> no matvec, no wait)
    if (tid < SROW) {
        float v = tanhf(g_xp[row0 + tid]);
        st_f32_rlx(&g_hv[1][row0 + tid], v);
        g_hs[row0 + tid] = v;
    }
    __syncwarp();
    if (tid == 0) {
        __threadfence();
        st_u32_rlx(&g_flag[blockIdx.x][0], 1u);
    }

    for (int s = 1; s < SEQ; s++) {
        const int slot = s & 1;
        const int ns   = (s + 1) & 1;
        // prefetch xp (independent of h -> overlaps the wait)
        float xpv = 0.f;
        if (tid < SROW) xpv = __ldcg(&g_xp[(size_t)s * HID + row0 + tid]);

        // detect + stage: thread t (<128) gates rows 8t..8t+7 via flag[t]
        if (tid < SCTA) {
            const unsigned* f = &g_flag[tid][0];
            unsigned u = ld_u32_rlx(f);
            int spins = 0;
            while (u < (unsigned)s) {
                if (++spins > 32) __nanosleep(20);
                u = ld_u32_rlx(f);
            }
            __threadfence();
            const float* src = &g_hv[slot][tid * 8];
            float v0 = ld_f32_rlx(src + 0), v1 = ld_f32_rlx(src + 1);
            float v2 = ld_f32_rlx(src + 2), v3 = ld_f32_rlx(src + 3);
            float v4 = ld_f32_rlx(src + 4), v5 = ld_f32_rlx(src + 5);
            float v6 = ld_f32_rlx(src + 6), v7 = ld_f32_rlx(src + 7);
            float* dst = &sh[tid * 8];
            dst[0] = v0; dst[1] = v1; dst[2] = v2; dst[3] = v3;
            dst[4] = v4; dst[5] = v5; dst[6] = v6; dst[7] = v7;
        }
        __syncthreads();   // bar0: sh fully staged

        if (is_compute) {
            const float4 h0 = *(const float4*)&sh[c0];
            const float4 h1 = *(const float4*)&sh[c0 + 4];
            float a0 = w0a.x*h0.x + w0a.y*h0.y + w0a.z*h0.z + w0a.w*h0.w
                     + w0b.x*h1.x + w0b.y*h1.y + w0b.z*h1.z + w0b.w*h1.w;
            float a1 = w1a.x*h0.x + w1a.y*h0.y + w1a.z*h0.z + w1a.w*h0.w
                     + w1b.x*h1.x + w1b.y*h1.y + w1b.z*h1.z + w1b.w*h1.w;
            #pragma unroll
            for (int off = 16; off > 0; off >>= 1) {
                a0 += __shfl_xor_sync(0xffffffffu, a0, off);
                a1 += __shfl_xor_sync(0xffffffffu, a1, off);
            }
            if (l == 0) {
                sred[2 * p    ][q] = a0;
                sred[2 * p + 1][q] = a1;
            }
        }
        __syncthreads();   // bar1: sred ready

        // finalize 8 rows, publish h_{s+1} (values then fenced flag)
        if (tid < SROW) {
            const float4 sr = *(const float4*)&sred[tid][0];
            const float v = tanhf(xpv + ((sr.x + sr.y) + (sr.z + sr.w)));
            st_f32_rlx(&g_hv[ns][row0 + tid], v);
            g_hs[(size_t)s * HID + row0 + tid] = v;
        }
        __syncwarp();
        if (tid == 0) {
            __threadfence();
            st_u32_rlx(&g_flag[blockIdx.x][0], (unsigned)(s + 1));
        }
    }
}

// ---------------- h_last epilogue ----------------
__global__ void copy_hlast_kernel(float* __restrict__ out) {
    const int i = threadIdx.x;                 // 1024 threads
    out[(size_t)SEQ * NCH + i] = g_hv[0][i];   // S even -> slot 0
}

// ---------------- launch ----------------
extern "C" void kernel_launch(void* const* d_in, const int* in_sizes, int n_in,
                              void* d_out, int out_size)
{
    const int*   input_seq = (const int*)  d_in[0];
    const float* emb       = (const float*)d_in[1];
    const float* Wax       = (const float*)d_in[2];
    const float* Waa       = (const float*)d_in[3];
    const float* Wya       = (const float*)d_in[4];
    const float* b_y       = (const float*)d_in[5];
    float* out = (float*)d_out;

    float* xp_ptr = nullptr;
    float* hs_ptr = nullptr;
    cudaGetSymbolAddress((void**)&xp_ptr, g_xp);
    cudaGetSymbolAddress((void**)&hs_ptr, g_hs);

    // 1) x_proj[s,h] = sum_e emb_table[input_seq[s],e] * Wax[h,e]
    {
        dim3 grid(HID / 128, SEQ / 128);
        sgemm_tn<true, false><<<grid, 256>>>(emb, Wax, xp_ptr, input_seq, nullptr,
                                             SEQ, HID, EMB);
    }
    // 2) reset flags, then the sequential scan
    init_tags_kernel<<<1, 256>>>();
    scan_kernel<<<SCTA, 1024>>>(Waa);
    // 3) out[s,v] = sum_h hs[s,h] * Wya[v,h] + b_y[v]
    {
        dim3 grid(NCH / 128, SEQ / 128);
        sgemm_tn<false, true><<<grid, 256>>>(hs_ptr, Wya, out, nullptr, b_y,
                                             SEQ, NCH, HID);
    }
    // 4) append h_last
    copy_hlast_kernel<<<1, HID>>>(out);
}

// round 17
// speedup vs baseline: 3.1962x; 3.1962x over previous
#include <cuda_runtime.h>
#include <cuda_bf16.h>
#include <cstdint>

#define SEQ   65536
#define HID   1024
#define EMB   512
#define NCH   512
#define SCTA  128        // scan CTAs
#define SROW  8          // rows per scan CTA

// ---------------- device scratch (static allocation only) ----------------
struct __align__(8) Pub { unsigned int v; unsigned int tag; };
__device__ Pub   g_h[2][HID];                    // ping-pong (value,tag) pairs
__device__ float g_xp[(size_t)SEQ * HID];        // x projections  (256 MB)
__device__ float g_hs[(size_t)SEQ * HID];        // hidden states  (256 MB)

// ---------------- small helpers (proven: R2/R9/R12/R15) ----------------
__device__ __forceinline__ void st_pair(Pub* p, float val, unsigned tag) {
    unsigned long long u = ((unsigned long long)tag << 32) |
                           (unsigned long long)__float_as_uint(val);
    asm volatile("st.global.relaxed.gpu.b64 [%0], %1;" :: "l"(p), "l"(u) : "memory");
}
__device__ __forceinline__ unsigned long long ld_pair(const Pub* p) {
    unsigned long long u;
    asm volatile("ld.global.relaxed.gpu.b64 %0, [%1];" : "=l"(u) : "l"(p) : "memory");
    return u;
}
// depth-2 pipelined wait: two outstanding loads to the same pair, phase-
// staggered, checked alternately -> sampling period ~RTT/2 instead of ~RTT.
__device__ __forceinline__ float wait_pair2(const Pub* p, unsigned s) {
    unsigned long long a = ld_pair(p);
    __nanosleep(80);                       // offset second stream ~1/4 RTT
    unsigned long long b = ld_pair(p);
    int spins = 0;
    for (;;) {
        if ((unsigned)(a >> 32) == s) return __uint_as_float((unsigned)a);
        a = ld_pair(p);                    // re-issue stream A
        if ((unsigned)(b >> 32) == s) return __uint_as_float((unsigned)b);
        b = ld_pair(p);                    // re-issue stream B
        if (++spins > 64) __nanosleep(40); // safety backoff
    }
}

// ---------------- init: clear tags each launch (graph replays!) ----------------
__global__ void init_tags_kernel() {
    unsigned long long* p = (unsigned long long*)g_h;
    for (int i = threadIdx.x; i < 2 * HID; i += blockDim.x) p[i] = 0ULL;
}

// ---------------- fp32 SGEMM:  C[M,N] = A[M,K] * B[N,K]^T (+bias) ----------------
template<bool GATHER, bool BIAS>
__global__ void __launch_bounds__(256) sgemm_tn(
    const float* __restrict__ A, const float* __restrict__ B,
    float* __restrict__ C, const int* __restrict__ idx,
    const float* __restrict__ bias, int M, int N, int K)
{
    __shared__ __align__(16) float As[8][132];
    __shared__ __align__(16) float Bs[8][132];
    __shared__ int sidx[128];

    const int tid = threadIdx.x;
    const int bm  = blockIdx.y * 128;
    const int bn  = blockIdx.x * 128;

    if (GATHER && tid < 128) sidx[tid] = idx[bm + tid];
    __syncthreads();

    const int tx = tid & 15;          // 0..15 -> n
    const int ty = tid >> 4;          // 0..15 -> m
    const int arow = tid >> 1;        // 0..127
    const int akq  = (tid & 1) * 4;   // 0 or 4

    const float* Arow = GATHER ? (A + (size_t)sidx[arow] * K)
                               : (A + (size_t)(bm + arow) * K);
    const float* Brow = B + (size_t)(bn + arow) * K;

    float acc[8][8];
    #pragma unroll
    for (int i = 0; i < 8; i++)
        #pragma unroll
        for (int j = 0; j < 8; j++) acc[i][j] = 0.f;

    for (int kt = 0; kt < K; kt += 8) {
        float4 av = *(const float4*)(Arow + kt + akq);
        float4 bv = *(const float4*)(Brow + kt + akq);
        __syncthreads();
        As[akq+0][arow] = av.x; As[akq+1][arow] = av.y;
        As[akq+2][arow] = av.z; As[akq+3][arow] = av.w;
        Bs[akq+0][arow] = bv.x; Bs[akq+1][arow] = bv.y;
        Bs[akq+2][arow] = bv.z; Bs[akq+3][arow] = bv.w;
        __syncthreads();
        #pragma unroll
        for (int k = 0; k < 8; k++) {
            float ra[8], rb[8];
            #pragma unroll
            for (int i = 0; i < 8; i++) ra[i] = As[k][ty * 8 + i];
            #pragma unroll
            for (int j = 0; j < 8; j++) rb[j] = Bs[k][tx * 8 + j];
            #pragma unroll
            for (int i = 0; i < 8; i++)
                #pragma unroll
                for (int j = 0; j < 8; j++) acc[i][j] += ra[i] * rb[j];
        }
    }

    float bload[8];
    #pragma unroll
    for (int j = 0; j < 8; j++) bload[j] = BIAS ? bias[bn + tx * 8 + j] : 0.f;

    #pragma unroll
    for (int i = 0; i < 8; i++) {
        size_t row = (size_t)(bm + ty * 8 + i);
        float* cp = C + row * N + bn + tx * 8;
        float4 v0, v1;
        v0.x = acc[i][0] + bload[0]; v0.y = acc[i][1] + bload[1];
        v0.z = acc[i][2] + bload[2]; v0.w = acc[i][3] + bload[3];
        v1.x = acc[i][4] + bload[4]; v1.y = acc[i][5] + bload[5];
        v1.z = acc[i][6] + bload[6]; v1.w = acc[i][7] + bload[7];
        *(float4*)(cp)     = v0;
        *(float4*)(cp + 4) = v1;
    }
}

// ---------------- the scan ----------------
// EXACT R2 structure (measured best: 74.3 ms). 128 CTAs x 1024 threads,
// 8 rows per CTA. The ONLY change vs R2: wait_pair -> wait_pair2
// (depth-2 pipelined poll, halves sampling period of the detect).
//   Staging: thread tid polls pair tid into sh (1 pair each).
//   Compute: warps 0..15. Row-pair p = w>>2 (local rows 2p,2p+1), quarter
//   q = w&3; lane l covers cols [strip*8, +8), strip = q*32+l (LDS.128,
//   h read 4x => 16KB crossbar/step). Butterfly, lane 0 -> sred[2p..2p+1][q].
//   bar1, then threads tid<8 combine 4 partials, tanh, publish (64B
//   coalesced).
// Hazards (2 full barriers/step): sh staging(s+1) occurs after bar1(s); all
// sh reads of step s precede bar1(s). sred writes(s+1) occur after
// bar0(s+1), which finalize threads reach only after their sred reads(s).
__global__ void __launch_bounds__(1024, 1) scan_kernel(const float* __restrict__ Waa)
{
    __shared__ __align__(16) float sh[HID];          // staged h_t
    __shared__ float sred[SROW][4];                  // [row][quarter]

    const int tid = threadIdx.x;
    const int w = tid >> 5, l = tid & 31;
    const int row0 = blockIdx.x * SROW;
    const bool is_compute = (w < 16);
    const int p = (w >> 2) & 3;          // row-pair 0..3
    const int q = w & 3;                 // column quarter
    const int strip = q * 32 + l;        // column strip 0..127
    const int c0 = strip * 8;            // this lane's column base

    // weights: 2 rows x 8 cols per compute thread (coalesced one-time load)
    float4 w0a, w0b, w1a, w1b;
    if (is_compute) {
        const float* base = Waa + (size_t)(row0 + 2 * p) * HID + c0;
        w0a = *(const float4*)(base);
        w0b = *(const float4*)(base + 4);
        w1a = *(const float4*)(base + HID);
        w1b = *(const float4*)(base + HID + 4);
    }

    // step 0: h_1 = tanh(xp[0]) (h_0 == 0 -> no matvec, no wait)
    if (tid < SROW) {
        float v = tanhf(g_xp[row0 + tid]);
        st_pair(&g_h[1][row0 + tid], v, 1u);
        g_hs[row0 + tid] = v;
    }

    for (int s = 1; s < SEQ; s++) {
        const int slot = s & 1;
        // prefetch xp (independent of h -> overlaps the wait)
        float xpv = 0.f;
        if (tid < SROW) xpv = __ldcg(&g_xp[(size_t)s * HID + row0 + tid]);

        // stage h_s: one pair per thread, depth-2 pipelined detect
        sh[tid] = wait_pair2(&g_h[slot][tid], (unsigned)s);
        __syncthreads();   // bar0: sh fully staged

        if (is_compute) {
            const float4 h0 = *(const float4*)&sh[c0];
            const float4 h1 = *(const float4*)&sh[c0 + 4];
            float a0 = w0a.x*h0.x + w0a.y*h0.y + w0a.z*h0.z + w0a.w*h0.w
                     + w0b.x*h1.x + w0b.y*h1.y + w0b.z*h1.z + w0b.w*h1.w;
            float a1 = w1a.x*h0.x + w1a.y*h0.y + w1a.z*h0.z + w1a.w*h0.w
                     + w1b.x*h1.x + w1b.y*h1.y + w1b.z*h1.z + w1b.w*h1.w;
            #pragma unroll
            for (int off = 16; off > 0; off >>= 1) {
                a0 += __shfl_xor_sync(0xffffffffu, a0, off);
                a1 += __shfl_xor_sync(0xffffffffu, a1, off);
            }
            if (l == 0) {
                sred[2 * p    ][q] = a0;
                sred[2 * p + 1][q] = a1;
            }
        }
        __syncthreads();   // bar1: sred ready

        // finalize 8 rows, publish h_{s+1} (64B coalesced)
        if (tid < SROW) {
            const float sum = xpv + sred[tid][0] + sred[tid][1]
                                  + sred[tid][2] + sred[tid][3];
            const float v = tanhf(sum);
            st_pair(&g_h[(s + 1) & 1][row0 + tid], v, (unsigned)(s + 1));
            g_hs[(size_t)s * HID + row0 + tid] = v;
        }
    }
}

// ---------------- h_last epilogue ----------------
__global__ void copy_hlast_kernel(float* __restrict__ out) {
    const int i = threadIdx.x;                 // 1024 threads
    out[(size_t)SEQ * NCH + i] = __uint_as_float(g_h[0][i].v);  // S even -> slot 0
}

// ---------------- launch ----------------
extern "C" void kernel_launch(void* const* d_in, const int* in_sizes, int n_in,
                              void* d_out, int out_size)
{
    const int*   input_seq = (const int*)  d_in[0];
    const float* emb       = (const float*)d_in[1];
    const float* Wax       = (const float*)d_in[2];
    const float* Waa       = (const float*)d_in[3];
    const float* Wya       = (const float*)d_in[4];
    const float* b_y       = (const float*)d_in[5];
    float* out = (float*)d_out;

    float* xp_ptr = nullptr;
    float* hs_ptr = nullptr;
    cudaGetSymbolAddress((void**)&xp_ptr, g_xp);
    cudaGetSymbolAddress((void**)&hs_ptr, g_hs);

    // 1) x_proj[s,h] = sum_e emb_table[input_seq[s],e] * Wax[h,e]
    {
        dim3 grid(HID / 128, SEQ / 128);
        sgemm_tn<true, false><<<grid, 256>>>(emb, Wax, xp_ptr, input_seq, nullptr,
                                             SEQ, HID, EMB);
    }
    // 2) reset publish tags, then the sequential scan
    init_tags_kernel<<<1, 256>>>();
    scan_kernel<<<SCTA, 1024>>>(Waa);
    // 3) out[s,v] = sum_h hs[s,h] * Wya[v,h] + b_y[v]
    {
        dim3 grid(NCH / 128, SEQ / 128);
        sgemm_tn<false, true><<<grid, 256>>>(hs_ptr, Wya, out, nullptr, b_y,
                                             SEQ, NCH, HID);
    }
    // 4) append h_last
    copy_hlast_kernel<<<1, HID>>>(out);
}